// round 12
// baseline (speedup 1.0000x reference)
#include <cuda_runtime.h>
#include <cmath>

#define NMAX 20000

__device__ float g_PHI[NMAX * 32];
__device__ float g_ENV[NMAX];
__device__ float g_F[NMAX * 192];

// ---------------------------------------------------------------------------
// Edge kernel (R4-proven artifact): scatter env-weighted RBF vector + env.
// ---------------------------------------------------------------------------
__global__ void edge_kernel(const float* __restrict__ dist,
                            const int* __restrict__ nb, int E,
                            float mu0, float delta, float inv_delta,
                            float beta, float c2, float q)
{
    int e = blockIdx.x * blockDim.x + threadIdx.x;
    if (e >= E) return;
    float d = dist[e];
    int j = nb[e];
    float env = 0.0f;
    if (d < 5.0f) env = 0.5f * (__cosf(0.62831853071795864769f * d) + 1.0f);
    atomicAdd(&g_ENV[j], env);

    float t = __expf(-d);
    int r0 = (int)floorf((t - mu0) * inv_delta + 0.5f);
    r0 = max(0, min(31, r0));
    float u0 = t - (mu0 + delta * (float)r0);
    float p0 = env * __expf(-beta * u0 * u0);
    float* phr = g_PHI + (size_t)j * 32;
    const float THR = 1e-6f;
    if (p0 > THR) atomicAdd(&phr[r0], p0);

    float w = __expf(c2 * (t - (mu0 + delta * ((float)r0 + 0.5f))));
    float p = p0;
    for (int r = r0 + 1; r < 32; ++r) {
        p *= w; w *= q;
        if (p <= THR) break;
        atomicAdd(&phr[r], p);
    }
    w = __expf(-c2 * (t - (mu0 + delta * ((float)r0 - 0.5f))));
    p = p0;
    for (int r = r0 - 1; r >= 0; --r) {
        p *= w; w *= q;
        if (p <= THR) break;
        atomicAdd(&phr[r], p);
    }
}

// ---------------------------------------------------------------------------
// Coefficient kernel: F[n,o] = env[n]*bd[o] + Wd[o,:] . phi[n,:]
// ---------------------------------------------------------------------------
__global__ void coeff_kernel(const float* __restrict__ Wd,
                             const float* __restrict__ bd, int N)
{
    __shared__ float ph[32];
    int n = blockIdx.x;
    int o = threadIdx.x;
    if (o < 32) ph[o] = g_PHI[(size_t)n * 32 + o];
    __syncthreads();
    float acc = g_ENV[n] * bd[o];
    const float4* w = (const float4*)(Wd + (size_t)o * 32);
    #pragma unroll
    for (int r4 = 0; r4 < 8; ++r4) {
        float4 wv = w[r4];
        acc += wv.x * ph[4 * r4] + wv.y * ph[4 * r4 + 1]
             + wv.z * ph[4 * r4 + 2] + wv.w * ph[4 * r4 + 3];
    }
    g_F[(size_t)n * 192 + o] = acc;
}

// ---------------------------------------------------------------------------
// f32x2 packed FMA helpers
// ---------------------------------------------------------------------------
__device__ __forceinline__ void ffma2(unsigned long long& d,
                                      unsigned long long a,
                                      unsigned long long b)
{
    asm("fma.rn.f32x2 %0, %1, %2, %0;" : "+l"(d) : "l"(a), "l"(b));
}
__device__ __forceinline__ float sum2(unsigned long long v)
{
    float lo, hi;
    asm("mov.b64 {%0, %1}, %2;" : "=f"(lo), "=f"(hi) : "l"(v));
    return lo + hi;
}

__device__ __forceinline__ void decomp9(const float x[9], float* iso,
                                        float a[3], float s[5])
{
    float m = (x[0] + x[4] + x[8]) * (1.0f / 3.0f);
    *iso = m;
    a[0] = 0.5f * (x[1] - x[3]);
    a[1] = 0.5f * (x[2] - x[6]);
    a[2] = 0.5f * (x[5] - x[7]);
    s[0] = x[0] - m;
    s[1] = 0.5f * (x[1] + x[3]);
    s[2] = 0.5f * (x[2] + x[6]);
    s[3] = x[4] - m;
    s[4] = 0.5f * (x[5] + x[7]);
}

__device__ __forceinline__ void build9(float iso, const float a[3],
                                       const float s[5], float Y[9])
{
    Y[0] = iso + s[0];        Y[1] = a[0] + s[1];       Y[2] = a[1] + s[2];
    Y[3] = s[1] - a[0];       Y[4] = iso + s[3];        Y[5] = a[2] + s[4];
    Y[6] = s[2] - a[1];       Y[7] = s[4] - a[2];       Y[8] = iso - s[0] - s[3];
}

// ---------------------------------------------------------------------------
// Node kernel: 16 warps = 8 pairs, GRP=2 nodes/pair, 512 threads (128-reg cap)
// K-SPLIT mixes (R11) + preserved-M in SMEM (cpM) instead of registers (fixes
// R11's over-cap register carrying). Each comp plane read by exactly one warp.
// ---------------------------------------------------------------------------
#define NPAIR 8
#define GRP 2
#define WROW 68
#define PLANE 68
#define CPSZ (9 * PLANE)            // 612 per node
#define OFF_W    0                  // 6 * 64 * 68 = 26112
#define OFF_PAIR 26112
#define PSZ      3028               // cp 1224 | cpM 1224 | xs 576 | pad 4
#define SMEM_FLOATS (OFF_PAIR + NPAIR * PSZ)   // 50,336 floats = 201,344 B

#define PAIR_BAR() asm volatile("bar.sync %0, 64;" :: "r"(barid) : "memory")

// One mix stage. Reads comp planes from cp, writes Y back into cp.
// warp0 (half==0): A planes 0..2 + iso plane 8; warp1: S planes 3..7.
// Balanced: per-warp LDS wavefronts 192 vs 192.
__device__ __forceinline__ void mix_stage(const float* __restrict__ smWA,
                                          const float* __restrict__ smWS,
                                          const float* __restrict__ smWI,
                                          float* __restrict__ cp,
                                          int lane, int half)
{
    if (half == 0) {
        unsigned long long accA[3][2][GRP] = {};
        unsigned long long accI[2][GRP] = {};
        const float* wA0 = smWA + lane * WROW;
        const float* wA1 = smWA + (lane + 32) * WROW;
        const float* wI0 = smWI + lane * WROW;
        const float* wI1 = smWI + (lane + 32) * WROW;
        #pragma unroll 4
        for (int j = 0; j < 16; ++j) {
            ulonglong2 a0 = *(const ulonglong2*)(wA0 + 4 * j);
            ulonglong2 a1 = *(const ulonglong2*)(wA1 + 4 * j);
            ulonglong2 i0 = *(const ulonglong2*)(wI0 + 4 * j);
            ulonglong2 i1 = *(const ulonglong2*)(wI1 + 4 * j);
            #pragma unroll
            for (int n = 0; n < GRP; ++n) {
                const float* base = cp + n * CPSZ + 4 * j;
                #pragma unroll
                for (int k = 0; k < 3; ++k) {
                    ulonglong2 m = *(const ulonglong2*)(base + k * PLANE);
                    ffma2(accA[k][0][n], a0.x, m.x);
                    ffma2(accA[k][0][n], a0.y, m.y);
                    ffma2(accA[k][1][n], a1.x, m.x);
                    ffma2(accA[k][1][n], a1.y, m.y);
                }
                ulonglong2 m8 = *(const ulonglong2*)(base + 8 * PLANE);
                ffma2(accI[0][n], i0.x, m8.x);
                ffma2(accI[0][n], i0.y, m8.y);
                ffma2(accI[1][n], i1.x, m8.x);
                ffma2(accI[1][n], i1.y, m8.y);
            }
        }
        __syncwarp();
        #pragma unroll
        for (int n = 0; n < GRP; ++n) {
            float* cpn = cp + n * CPSZ;
            #pragma unroll
            for (int h = 0; h < 2; ++h) {
                int ch = lane + 32 * h;
                cpn[0 * PLANE + ch] = sum2(accA[0][h][n]);
                cpn[1 * PLANE + ch] = sum2(accA[1][h][n]);
                cpn[2 * PLANE + ch] = sum2(accA[2][h][n]);
                cpn[8 * PLANE + ch] = sum2(accI[h][n]);
            }
        }
    } else {
        unsigned long long accS[5][2][GRP] = {};
        const float* wS0 = smWS + lane * WROW;
        const float* wS1 = smWS + (lane + 32) * WROW;
        #pragma unroll 4
        for (int j = 0; j < 16; ++j) {
            ulonglong2 s0 = *(const ulonglong2*)(wS0 + 4 * j);
            ulonglong2 s1 = *(const ulonglong2*)(wS1 + 4 * j);
            #pragma unroll
            for (int n = 0; n < GRP; ++n) {
                const float* base = cp + n * CPSZ + 3 * PLANE + 4 * j;
                #pragma unroll
                for (int k = 0; k < 5; ++k) {
                    ulonglong2 m = *(const ulonglong2*)(base + k * PLANE);
                    ffma2(accS[k][0][n], s0.x, m.x);
                    ffma2(accS[k][0][n], s0.y, m.y);
                    ffma2(accS[k][1][n], s1.x, m.x);
                    ffma2(accS[k][1][n], s1.y, m.y);
                }
            }
        }
        __syncwarp();
        #pragma unroll
        for (int n = 0; n < GRP; ++n) {
            float* cpn = cp + n * CPSZ;
            #pragma unroll
            for (int h = 0; h < 2; ++h) {
                int ch = lane + 32 * h;
                #pragma unroll
                for (int k = 0; k < 5; ++k)
                    cpn[(3 + k) * PLANE + ch] = sum2(accS[k][h][n]);
            }
        }
    }
}

__global__ __launch_bounds__(512, 1)
void node_kernel(const float* __restrict__ X,
    const float* __restrict__ WIa, const float* __restrict__ WAa, const float* __restrict__ WSa,
    const float* __restrict__ WIb, const float* __restrict__ WAb, const float* __restrict__ WSb,
    float* __restrict__ out, int N)
{
    extern __shared__ float sm[];
    int tid   = threadIdx.x;
    int warp  = tid >> 5;
    int lane  = tid & 31;
    int pair  = warp >> 1;
    int half  = warp & 1;
    int c     = lane + 32 * half;     // this thread's channel
    int pid   = tid & 63;
    int barid = pair + 1;

    // ---- stage weights (once per block) ----
    {
        const float* Ws[6] = {WAa, WSa, WIa, WAb, WSb, WIb};
        #pragma unroll
        for (int m = 0; m < 6; ++m) {
            const float* src = Ws[m];
            float* dst = sm + OFF_W + m * (64 * WROW);
            for (int idx = tid; idx < 4096; idx += 512)
                dst[(idx >> 6) * WROW + (idx & 63)] = src[idx];
        }
    }
    __syncthreads();

    float* cp  = sm + OFF_PAIR + pair * PSZ;      // mix in/out planes
    float* cpM = cp + GRP * CPSZ;                  // preserved M planes
    float* xs  = cpM + GRP * CPSZ;                 // 576 staging

    const float* smWA_a = sm + OFF_W + 0 * (64 * WROW);
    const float* smWS_a = sm + OFF_W + 1 * (64 * WROW);
    const float* smWI_a = sm + OFF_W + 2 * (64 * WROW);
    const float* smWA_b = sm + OFF_W + 3 * (64 * WROW);
    const float* smWS_b = sm + OFF_W + 4 * (64 * WROW);
    const float* smWI_b = sm + OFF_W + 5 * (64 * WROW);

    int Q = (N + GRP - 1) / GRP;
    int gp = blockIdx.x * NPAIR + pair;
    int step = gridDim.x * NPAIR;

    for (int q = gp; q < Q; q += step) {
        int n0 = q * GRP;

        // ---- per node: pair-cooperative stage X, decompose own channel ----
        #pragma unroll
        for (int n = 0; n < GRP; ++n) {
            int node = n0 + n;
            if (node < N) {
                const float4* src = (const float4*)(X + (size_t)node * 576);
                float4* dst = (float4*)xs;
                #pragma unroll
                for (int i = 0; i < 3; ++i) {
                    int idx = pid + 64 * i;
                    if (idx < 144) dst[idx] = src[idx];
                }
            }
            PAIR_BAR();
            {
                float x[9];
                #pragma unroll
                for (int k = 0; k < 9; ++k) x[k] = xs[c * 9 + k];
                float f = 0.0f;
                #pragma unroll
                for (int k = 0; k < 9; ++k) f += x[k] * x[k];
                float sc = __fdividef(1.0f, f + 1.0f);
                #pragma unroll
                for (int k = 0; k < 9; ++k) x[k] *= sc;
                float iso, a[3], s[5];
                decomp9(x, &iso, a, s);
                float m9[9];
                m9[0] = a[0]; m9[1] = a[1]; m9[2] = a[2];
                m9[3] = s[0]; m9[4] = s[1]; m9[5] = s[2];
                m9[6] = s[3]; m9[7] = s[4]; m9[8] = iso;
                float* cpn  = cp  + n * CPSZ;
                float* cpMn = cpM + n * CPSZ;
                #pragma unroll
                for (int k = 0; k < 9; ++k) {
                    cpn[k * PLANE + c]  = m9[k];
                    cpMn[k * PLANE + c] = m9[k];
                }
            }
            PAIR_BAR();
        }

        // ---- pre mix (k-split): cp planes overwritten with Y ----
        mix_stage(smWA_a, smWS_a, smWI_a, cp, lane, half);
        PAIR_BAR();

        // ---- sandwich: Z = YM + MY (M from cpM), normalize, decompose ----
        #pragma unroll
        for (int n = 0; n < GRP; ++n) {
            float* cpn  = cp  + n * CPSZ;
            float* cpMn = cpM + n * CPSZ;
            int node = n0 + n;
            int fnode = min(node, N - 1);
            const float* Fn = g_F + (size_t)fnode * 192;
            float fIv = Fn[c], fAv = Fn[64 + c], fSv = Fn[128 + c];

            float yv[9], mv[9];
            #pragma unroll
            for (int k = 0; k < 9; ++k) {
                yv[k] = cpn[k * PLANE + c];
                mv[k] = cpMn[k * PLANE + c];
            }
            float Y[9], M[9];
            build9(yv[8], &yv[0], &yv[3], Y);
            float mi = fIv * mv[8];
            float A[3] = {fAv * mv[0], fAv * mv[1], fAv * mv[2]};
            float S[5] = {fSv * mv[3], fSv * mv[4], fSv * mv[5],
                          fSv * mv[6], fSv * mv[7]};
            build9(mi, A, S, M);
            float Z[9];
            #pragma unroll
            for (int i = 0; i < 3; ++i)
                #pragma unroll
                for (int jj = 0; jj < 3; ++jj) {
                    float acc = 0.0f;
                    #pragma unroll
                    for (int k = 0; k < 3; ++k)
                        acc += Y[i * 3 + k] * M[k * 3 + jj]
                             + M[i * 3 + k] * Y[k * 3 + jj];
                    Z[i * 3 + jj] = acc;
                }
            float nrm = 0.0f;
            #pragma unroll
            for (int k = 0; k < 9; ++k) { float v = Z[k] + 1.0f; nrm += v * v; }
            float inv = __fdividef(1.0f, nrm);
            #pragma unroll
            for (int k = 0; k < 9; ++k) Z[k] *= inv;
            float iso, a2[3], s2[5];
            decomp9(Z, &iso, a2, s2);
            cpn[0 * PLANE + c] = a2[0];
            cpn[1 * PLANE + c] = a2[1];
            cpn[2 * PLANE + c] = a2[2];
            cpn[3 * PLANE + c] = s2[0];
            cpn[4 * PLANE + c] = s2[1];
            cpn[5 * PLANE + c] = s2[2];
            cpn[6 * PLANE + c] = s2[3];
            cpn[7 * PLANE + c] = s2[4];
            cpn[8 * PLANE + c] = iso;
        }
        PAIR_BAR();

        // ---- post mix (k-split): cp planes overwritten with final Y ----
        mix_stage(smWA_b, smWS_b, smWI_b, cp, lane, half);
        PAIR_BAR();

        // ---- output: O = Y2 + Y2@Y2, stage per node, pair-coalesced store --
        #pragma unroll
        for (int n = 0; n < GRP; ++n) {
            int node = n0 + n;
            {
                float* cpn = cp + n * CPSZ;
                float yv[9];
                #pragma unroll
                for (int k = 0; k < 9; ++k) yv[k] = cpn[k * PLANE + c];
                float Y2[9];
                build9(yv[8], &yv[0], &yv[3], Y2);
                float* od = xs + c * 9;
                #pragma unroll
                for (int i = 0; i < 3; ++i)
                    #pragma unroll
                    for (int jj = 0; jj < 3; ++jj) {
                        float acc = Y2[i * 3 + jj];
                        #pragma unroll
                        for (int k = 0; k < 3; ++k)
                            acc += Y2[i * 3 + k] * Y2[k * 3 + jj];
                        od[i * 3 + jj] = acc;
                    }
            }
            PAIR_BAR();
            if (node < N) {
                float4* dst = (float4*)(out + (size_t)node * 576);
                const float4* src = (const float4*)xs;
                #pragma unroll
                for (int i = 0; i < 3; ++i) {
                    int idx = pid + 64 * i;
                    if (idx < 144) dst[idx] = src[idx];
                }
            }
            PAIR_BAR();
        }
    }
}

// ---------------------------------------------------------------------------
extern "C" void kernel_launch(void* const* d_in, const int* in_sizes, int n_in,
                              void* d_out, int out_size)
{
    const float* X    = (const float*)d_in[0];
    const float* dist = (const float*)d_in[1];
    const int*   nb   = (const int*)d_in[2];
    const float* WIa  = (const float*)d_in[3];
    const float* WAa  = (const float*)d_in[4];
    const float* WSa  = (const float*)d_in[5];
    const float* WIb  = (const float*)d_in[6];
    const float* WAb  = (const float*)d_in[7];
    const float* WSb  = (const float*)d_in[8];
    const float* Wd   = (const float*)d_in[9];
    const float* bd   = (const float*)d_in[10];
    float* out = (float*)d_out;

    int N = in_sizes[0] / 576;
    int E = in_sizes[1];

    void* phi_ptr = nullptr;
    void* env_ptr = nullptr;
    cudaGetSymbolAddress(&phi_ptr, g_PHI);
    cudaGetSymbolAddress(&env_ptr, g_ENV);
    cudaMemsetAsync(phi_ptr, 0, sizeof(float) * (size_t)N * 32, 0);
    cudaMemsetAsync(env_ptr, 0, sizeof(float) * (size_t)N, 0);

    double e5    = exp(-5.0);
    double delta = (1.0 - e5) / 31.0;
    double bb    = (2.0 / 32.0) * (1.0 - e5);
    double beta  = 1.0 / (bb * bb);
    float  c2    = (float)(2.0 * beta * delta);
    float  qf    = (float)exp(-2.0 * beta * delta * delta);

    edge_kernel<<<(E + 255) / 256, 256>>>(dist, nb, E,
        (float)e5, (float)delta, (float)(1.0 / delta), (float)beta, c2, qf);
    coeff_kernel<<<N, 192>>>(Wd, bd, N);

    static int smem_set = 0;
    if (!smem_set) {
        cudaFuncSetAttribute(node_kernel,
                             cudaFuncAttributeMaxDynamicSharedMemorySize,
                             SMEM_FLOATS * sizeof(float));
        smem_set = 1;
    }
    node_kernel<<<148, 512, SMEM_FLOATS * sizeof(float)>>>(
        X, WIa, WAa, WSa, WIb, WAb, WSb, out, N);
}

// round 13
// speedup vs baseline: 1.3149x; 1.3149x over previous
#include <cuda_runtime.h>
#include <cmath>

#define NMAX 20000

__device__ float g_PHI[NMAX * 32];
__device__ float g_ENV[NMAX];

// ---------------------------------------------------------------------------
// Edge kernel (R4-proven artifact): scatter env-weighted RBF vector + env.
// ---------------------------------------------------------------------------
__global__ void edge_kernel(const float* __restrict__ dist,
                            const int* __restrict__ nb, int E,
                            float mu0, float delta, float inv_delta,
                            float beta, float c2, float q)
{
    int e = blockIdx.x * blockDim.x + threadIdx.x;
    if (e >= E) return;
    float d = dist[e];
    int j = nb[e];
    float env = 0.0f;
    if (d < 5.0f) env = 0.5f * (__cosf(0.62831853071795864769f * d) + 1.0f);
    atomicAdd(&g_ENV[j], env);

    float t = __expf(-d);
    int r0 = (int)floorf((t - mu0) * inv_delta + 0.5f);
    r0 = max(0, min(31, r0));
    float u0 = t - (mu0 + delta * (float)r0);
    float p0 = env * __expf(-beta * u0 * u0);
    float* phr = g_PHI + (size_t)j * 32;
    const float THR = 1e-6f;
    if (p0 > THR) atomicAdd(&phr[r0], p0);

    float w = __expf(c2 * (t - (mu0 + delta * ((float)r0 + 0.5f))));
    float p = p0;
    for (int r = r0 + 1; r < 32; ++r) {
        p *= w; w *= q;
        if (p <= THR) break;
        atomicAdd(&phr[r], p);
    }
    w = __expf(-c2 * (t - (mu0 + delta * ((float)r0 - 0.5f))));
    p = p0;
    for (int r = r0 - 1; r >= 0; --r) {
        p *= w; w *= q;
        if (p <= THR) break;
        atomicAdd(&phr[r], p);
    }
}

// ---------------------------------------------------------------------------
// f32x2 packed FMA helpers
// ---------------------------------------------------------------------------
__device__ __forceinline__ void ffma2(unsigned long long& d,
                                      unsigned long long a,
                                      unsigned long long b)
{
    asm("fma.rn.f32x2 %0, %1, %2, %0;" : "+l"(d) : "l"(a), "l"(b));
}
__device__ __forceinline__ float sum2(unsigned long long v)
{
    float lo, hi;
    asm("mov.b64 {%0, %1}, %2;" : "=f"(lo), "=f"(hi) : "l"(v));
    return lo + hi;
}

__device__ __forceinline__ void decomp9(const float x[9], float* iso,
                                        float a[3], float s[5])
{
    float m = (x[0] + x[4] + x[8]) * (1.0f / 3.0f);
    *iso = m;
    a[0] = 0.5f * (x[1] - x[3]);
    a[1] = 0.5f * (x[2] - x[6]);
    a[2] = 0.5f * (x[5] - x[7]);
    s[0] = x[0] - m;
    s[1] = 0.5f * (x[1] + x[3]);
    s[2] = 0.5f * (x[2] + x[6]);
    s[3] = x[4] - m;
    s[4] = 0.5f * (x[5] + x[7]);
}

__device__ __forceinline__ void build9(float iso, const float a[3],
                                       const float s[5], float Y[9])
{
    Y[0] = iso + s[0];        Y[1] = a[0] + s[1];       Y[2] = a[1] + s[2];
    Y[3] = s[1] - a[0];       Y[4] = iso + s[3];        Y[5] = a[2] + s[4];
    Y[6] = s[2] - a[1];       Y[7] = s[4] - a[2];       Y[8] = iso - s[0] - s[3];
}

// ---------------------------------------------------------------------------
// Node kernel: 14 warps = 7 pairs, GRP=4 nodes/pair, 448 threads (146-reg cap)
// K-split mixes (each comp plane read by ONE warp), inline coefficient GEMV,
// and d_out used as M-scratch (folded f*comps written at decompose, read at
// sandwich by the SAME thread -> program-order safe; final store overwrites).
// ---------------------------------------------------------------------------
#define NPAIR 7
#define GRP 4
#define THREADS 448
#define WROW 68
#define PLANE 68
#define CPSZ (9 * PLANE)            // 612 per node
#define OFF_W    0                  // 6 * 64 * 68 = 26112
#define OFF_WDT  26112              // WdT[32][192] = 6144
#define OFF_PAIR 32256
#define PSZ      3160               // cp 4*612=2448 | xs 576 | phi 4*33=132 | pad
#define SMEM_FLOATS (OFF_PAIR + NPAIR * PSZ)   // 54,376 floats = 217,504 B

#define PAIR_BAR() asm volatile("bar.sync %0, 64;" :: "r"(barid) : "memory")

// One mix stage. Reads comp planes from cp, writes Y back into cp.
// warp0 (half==0): A planes 0..2 + iso plane 8 (both channel halves);
// warp1: S planes 3..7 (both channel halves).
__device__ __forceinline__ void mix_stage(const float* __restrict__ smWA,
                                          const float* __restrict__ smWS,
                                          const float* __restrict__ smWI,
                                          float* __restrict__ cp,
                                          int lane, int half)
{
    if (half == 0) {
        unsigned long long accA[3][2][GRP] = {};
        unsigned long long accI[2][GRP] = {};
        const float* wA0 = smWA + lane * WROW;
        const float* wA1 = smWA + (lane + 32) * WROW;
        const float* wI0 = smWI + lane * WROW;
        const float* wI1 = smWI + (lane + 32) * WROW;
        #pragma unroll 4
        for (int j = 0; j < 16; ++j) {
            ulonglong2 a0 = *(const ulonglong2*)(wA0 + 4 * j);
            ulonglong2 a1 = *(const ulonglong2*)(wA1 + 4 * j);
            ulonglong2 i0 = *(const ulonglong2*)(wI0 + 4 * j);
            ulonglong2 i1 = *(const ulonglong2*)(wI1 + 4 * j);
            #pragma unroll
            for (int n = 0; n < GRP; ++n) {
                const float* base = cp + n * CPSZ + 4 * j;
                #pragma unroll
                for (int k = 0; k < 3; ++k) {
                    ulonglong2 m = *(const ulonglong2*)(base + k * PLANE);
                    ffma2(accA[k][0][n], a0.x, m.x);
                    ffma2(accA[k][0][n], a0.y, m.y);
                    ffma2(accA[k][1][n], a1.x, m.x);
                    ffma2(accA[k][1][n], a1.y, m.y);
                }
                ulonglong2 m8 = *(const ulonglong2*)(base + 8 * PLANE);
                ffma2(accI[0][n], i0.x, m8.x);
                ffma2(accI[0][n], i0.y, m8.y);
                ffma2(accI[1][n], i1.x, m8.x);
                ffma2(accI[1][n], i1.y, m8.y);
            }
        }
        __syncwarp();
        #pragma unroll
        for (int n = 0; n < GRP; ++n) {
            float* cpn = cp + n * CPSZ;
            #pragma unroll
            for (int h = 0; h < 2; ++h) {
                int ch = lane + 32 * h;
                cpn[0 * PLANE + ch] = sum2(accA[0][h][n]);
                cpn[1 * PLANE + ch] = sum2(accA[1][h][n]);
                cpn[2 * PLANE + ch] = sum2(accA[2][h][n]);
                cpn[8 * PLANE + ch] = sum2(accI[h][n]);
            }
        }
    } else {
        unsigned long long accS[5][2][GRP] = {};
        const float* wS0 = smWS + lane * WROW;
        const float* wS1 = smWS + (lane + 32) * WROW;
        #pragma unroll 4
        for (int j = 0; j < 16; ++j) {
            ulonglong2 s0 = *(const ulonglong2*)(wS0 + 4 * j);
            ulonglong2 s1 = *(const ulonglong2*)(wS1 + 4 * j);
            #pragma unroll
            for (int n = 0; n < GRP; ++n) {
                const float* base = cp + n * CPSZ + 3 * PLANE + 4 * j;
                #pragma unroll
                for (int k = 0; k < 5; ++k) {
                    ulonglong2 m = *(const ulonglong2*)(base + k * PLANE);
                    ffma2(accS[k][0][n], s0.x, m.x);
                    ffma2(accS[k][0][n], s0.y, m.y);
                    ffma2(accS[k][1][n], s1.x, m.x);
                    ffma2(accS[k][1][n], s1.y, m.y);
                }
            }
        }
        __syncwarp();
        #pragma unroll
        for (int n = 0; n < GRP; ++n) {
            float* cpn = cp + n * CPSZ;
            #pragma unroll
            for (int h = 0; h < 2; ++h) {
                int ch = lane + 32 * h;
                #pragma unroll
                for (int k = 0; k < 5; ++k)
                    cpn[(3 + k) * PLANE + ch] = sum2(accS[k][h][n]);
            }
        }
    }
}

__global__ __launch_bounds__(THREADS, 1)
void node_kernel(const float* __restrict__ X,
    const float* __restrict__ WIa, const float* __restrict__ WAa, const float* __restrict__ WSa,
    const float* __restrict__ WIb, const float* __restrict__ WAb, const float* __restrict__ WSb,
    const float* __restrict__ Wd, const float* __restrict__ bd,
    float* __restrict__ out, int N)
{
    extern __shared__ float sm[];
    int tid   = threadIdx.x;
    int warp  = tid >> 5;
    int lane  = tid & 31;
    int pair  = warp >> 1;
    int half  = warp & 1;
    int c     = lane + 32 * half;     // this thread's channel
    int pid   = tid & 63;
    int barid = pair + 1;             // named barrier per pair (1..7)

    // ---- stage weights + WdT (once per block) ----
    {
        const float* Ws[6] = {WAa, WSa, WIa, WAb, WSb, WIb};
        #pragma unroll
        for (int m = 0; m < 6; ++m) {
            const float* src = Ws[m];
            float* dst = sm + OFF_W + m * (64 * WROW);
            for (int idx = tid; idx < 4096; idx += THREADS)
                dst[(idx >> 6) * WROW + (idx & 63)] = src[idx];
        }
        for (int idx = tid; idx < 6144; idx += THREADS) {
            int gc = idx >> 5, r = idx & 31;
            sm[OFF_WDT + r * 192 + gc] = Wd[idx];
        }
    }
    float bI = bd[c], bA = bd[64 + c], bS = bd[128 + c];
    __syncthreads();

    float* cp   = sm + OFF_PAIR + pair * PSZ;     // 4 * 612 comp planes
    float* xs   = cp + GRP * CPSZ;                 // 576 staging
    float* phis = xs + 576;                        // 4 * 33 (slot 32 = env)

    const float* smWA_a = sm + OFF_W + 0 * (64 * WROW);
    const float* smWS_a = sm + OFF_W + 1 * (64 * WROW);
    const float* smWI_a = sm + OFF_W + 2 * (64 * WROW);
    const float* smWA_b = sm + OFF_W + 3 * (64 * WROW);
    const float* smWS_b = sm + OFF_W + 4 * (64 * WROW);
    const float* smWI_b = sm + OFF_W + 5 * (64 * WROW);
    const float* smWdT  = sm + OFF_WDT;

    int Q = (N + GRP - 1) / GRP;
    int gp = blockIdx.x * NPAIR + pair;
    int step = gridDim.x * NPAIR;

    for (int q = gp; q < Q; q += step) {
        int n0 = q * GRP;

        // ---- stage phi + env (each warp stages 2 of the 4 nodes) ----
        #pragma unroll
        for (int t = 0; t < 2; ++t) {
            int n = half * 2 + t;
            int node = n0 + n;
            bool v = node < N;
            phis[n * 33 + lane] = v ? g_PHI[(size_t)node * 32 + lane] : 0.0f;
            if (lane == 0) phis[n * 33 + 32] = v ? g_ENV[node] : 0.0f;
        }
        PAIR_BAR();

        // ---- coefficient GEMV (weights amortized over the 4 nodes) ----
        float fI[GRP], fA[GRP], fS[GRP];
        #pragma unroll
        for (int n = 0; n < GRP; ++n) {
            float env = phis[n * 33 + 32];
            fI[n] = env * bI;
            fA[n] = env * bA;
            fS[n] = env * bS;
        }
        #pragma unroll 4
        for (int r = 0; r < 32; ++r) {
            const float* wr = smWdT + r * 192;
            float wi = wr[c], wa = wr[64 + c], ws = wr[128 + c];
            #pragma unroll
            for (int n = 0; n < GRP; ++n) {
                float p = phis[n * 33 + r];
                fI[n] += wi * p;
                fA[n] += wa * p;
                fS[n] += ws * p;
            }
        }

        // ---- per node: stage X, decompose -> cp planes + folded-M to out ---
        #pragma unroll
        for (int n = 0; n < GRP; ++n) {
            int node = n0 + n;
            if (node < N) {
                const float4* src = (const float4*)(X + (size_t)node * 576);
                float4* dst = (float4*)xs;
                #pragma unroll
                for (int i = 0; i < 3; ++i) {
                    int idx = pid + 64 * i;
                    if (idx < 144) dst[idx] = src[idx];
                }
            }
            PAIR_BAR();
            if (node < N) {
                float x[9];
                #pragma unroll
                for (int k = 0; k < 9; ++k) x[k] = xs[c * 9 + k];
                float f = 0.0f;
                #pragma unroll
                for (int k = 0; k < 9; ++k) f += x[k] * x[k];
                float sc = __fdividef(1.0f, f + 1.0f);
                #pragma unroll
                for (int k = 0; k < 9; ++k) x[k] *= sc;
                float iso, a[3], s[5];
                decomp9(x, &iso, a, s);
                float* cpn = cp + n * CPSZ;
                cpn[0 * PLANE + c] = a[0];
                cpn[1 * PLANE + c] = a[1];
                cpn[2 * PLANE + c] = a[2];
                cpn[3 * PLANE + c] = s[0];
                cpn[4 * PLANE + c] = s[1];
                cpn[5 * PLANE + c] = s[2];
                cpn[6 * PLANE + c] = s[3];
                cpn[7 * PLANE + c] = s[4];
                cpn[8 * PLANE + c] = iso;
                // folded M (f * comps) into out-scratch, plane-major coalesced
                float* mo = out + (size_t)node * 576;
                mo[0 * 64 + c] = fA[n] * a[0];
                mo[1 * 64 + c] = fA[n] * a[1];
                mo[2 * 64 + c] = fA[n] * a[2];
                mo[3 * 64 + c] = fS[n] * s[0];
                mo[4 * 64 + c] = fS[n] * s[1];
                mo[5 * 64 + c] = fS[n] * s[2];
                mo[6 * 64 + c] = fS[n] * s[3];
                mo[7 * 64 + c] = fS[n] * s[4];
                mo[8 * 64 + c] = fI[n] * iso;
            }
            PAIR_BAR();
        }

        // ---- pre mix (k-split): cp planes overwritten with Y ----
        mix_stage(smWA_a, smWS_a, smWI_a, cp, lane, half);
        PAIR_BAR();

        // ---- sandwich: Z = YM + MY (M from out-scratch), norm, decompose ---
        #pragma unroll
        for (int n = 0; n < GRP; ++n) {
            int node = n0 + n;
            if (node < N) {
                float* cpn = cp + n * CPSZ;
                const float* mo = out + (size_t)node * 576;
                float yv[9], mv[9];
                #pragma unroll
                for (int k = 0; k < 9; ++k) {
                    yv[k] = cpn[k * PLANE + c];
                    mv[k] = mo[k * 64 + c];     // same thread wrote it
                }
                float Y[9], M[9];
                build9(yv[8], &yv[0], &yv[3], Y);
                build9(mv[8], &mv[0], &mv[3], M);
                float Z[9];
                #pragma unroll
                for (int i = 0; i < 3; ++i)
                    #pragma unroll
                    for (int jj = 0; jj < 3; ++jj) {
                        float acc = 0.0f;
                        #pragma unroll
                        for (int k = 0; k < 3; ++k)
                            acc += Y[i * 3 + k] * M[k * 3 + jj]
                                 + M[i * 3 + k] * Y[k * 3 + jj];
                        Z[i * 3 + jj] = acc;
                    }
                float nrm = 0.0f;
                #pragma unroll
                for (int k = 0; k < 9; ++k) { float v = Z[k] + 1.0f; nrm += v * v; }
                float inv = __fdividef(1.0f, nrm);
                #pragma unroll
                for (int k = 0; k < 9; ++k) Z[k] *= inv;
                float iso, a2[3], s2[5];
                decomp9(Z, &iso, a2, s2);
                cpn[0 * PLANE + c] = a2[0];
                cpn[1 * PLANE + c] = a2[1];
                cpn[2 * PLANE + c] = a2[2];
                cpn[3 * PLANE + c] = s2[0];
                cpn[4 * PLANE + c] = s2[1];
                cpn[5 * PLANE + c] = s2[2];
                cpn[6 * PLANE + c] = s2[3];
                cpn[7 * PLANE + c] = s2[4];
                cpn[8 * PLANE + c] = iso;
            }
        }
        PAIR_BAR();

        // ---- post mix (k-split): cp planes overwritten with final Y ----
        mix_stage(smWA_b, smWS_b, smWI_b, cp, lane, half);
        PAIR_BAR();

        // ---- output: O = Y2 + Y2@Y2, stage per node, pair-coalesced store --
        #pragma unroll
        for (int n = 0; n < GRP; ++n) {
            int node = n0 + n;
            {
                float* cpn = cp + n * CPSZ;
                float yv[9];
                #pragma unroll
                for (int k = 0; k < 9; ++k) yv[k] = cpn[k * PLANE + c];
                float Y2[9];
                build9(yv[8], &yv[0], &yv[3], Y2);
                float* od = xs + c * 9;
                #pragma unroll
                for (int i = 0; i < 3; ++i)
                    #pragma unroll
                    for (int jj = 0; jj < 3; ++jj) {
                        float acc = Y2[i * 3 + jj];
                        #pragma unroll
                        for (int k = 0; k < 3; ++k)
                            acc += Y2[i * 3 + k] * Y2[k * 3 + jj];
                        od[i * 3 + jj] = acc;
                    }
            }
            PAIR_BAR();
            if (node < N) {
                float4* dst = (float4*)(out + (size_t)node * 576);
                const float4* src = (const float4*)xs;
                #pragma unroll
                for (int i = 0; i < 3; ++i) {
                    int idx = pid + 64 * i;
                    if (idx < 144) dst[idx] = src[idx];
                }
            }
            PAIR_BAR();
        }
    }
}

// ---------------------------------------------------------------------------
extern "C" void kernel_launch(void* const* d_in, const int* in_sizes, int n_in,
                              void* d_out, int out_size)
{
    const float* X    = (const float*)d_in[0];
    const float* dist = (const float*)d_in[1];
    const int*   nb   = (const int*)d_in[2];
    const float* WIa  = (const float*)d_in[3];
    const float* WAa  = (const float*)d_in[4];
    const float* WSa  = (const float*)d_in[5];
    const float* WIb  = (const float*)d_in[6];
    const float* WAb  = (const float*)d_in[7];
    const float* WSb  = (const float*)d_in[8];
    const float* Wd   = (const float*)d_in[9];
    const float* bd   = (const float*)d_in[10];
    float* out = (float*)d_out;

    int N = in_sizes[0] / 576;
    int E = in_sizes[1];

    void* phi_ptr = nullptr;
    void* env_ptr = nullptr;
    cudaGetSymbolAddress(&phi_ptr, g_PHI);
    cudaGetSymbolAddress(&env_ptr, g_ENV);
    cudaMemsetAsync(phi_ptr, 0, sizeof(float) * (size_t)N * 32, 0);
    cudaMemsetAsync(env_ptr, 0, sizeof(float) * (size_t)N, 0);

    double e5    = exp(-5.0);
    double delta = (1.0 - e5) / 31.0;
    double bb    = (2.0 / 32.0) * (1.0 - e5);
    double beta  = 1.0 / (bb * bb);
    float  c2    = (float)(2.0 * beta * delta);
    float  qf    = (float)exp(-2.0 * beta * delta * delta);

    edge_kernel<<<(E + 255) / 256, 256>>>(dist, nb, E,
        (float)e5, (float)delta, (float)(1.0 / delta), (float)beta, c2, qf);

    static int smem_set = 0;
    if (!smem_set) {
        cudaFuncSetAttribute(node_kernel,
                             cudaFuncAttributeMaxDynamicSharedMemorySize,
                             SMEM_FLOATS * sizeof(float));
        smem_set = 1;
    }
    node_kernel<<<148, THREADS, SMEM_FLOATS * sizeof(float)>>>(
        X, WIa, WAa, WSa, WIb, WAb, WSb, Wd, bd, out, N);
}